// round 4
// baseline (speedup 1.0000x reference)
#include <cuda_runtime.h>

#define VD 160
#define VH 192
#define VW 160
#define NB 2
#define NVOX (VD * VH * VW)          // 4,915,200 voxels per batch
#define NTOT (NB * NVOX)             // 9,830,400

// Ping-pong scratch (118 MB). Static device global: allowed by harness rules.
__device__ float g_scratch[(size_t)NTOT * 3];

__global__ void __launch_bounds__(256)
vint_step(const float* __restrict__ src, float* __restrict__ dst, float scale)
{
    unsigned idx = blockIdx.x * 256u + threadIdx.x;
    if (idx >= (unsigned)NTOT) return;

    unsigned z = idx % VW;
    unsigned t = idx / VW;
    unsigned y = t % VH;
    t /= VH;
    unsigned x = t % VD;
    unsigned b = t / VD;

    const float* __restrict__ vol = src + (size_t)b * NVOX * 3;
    unsigned vo = ((x * VH + y) * VW + z) * 3;

    // Center displacement (this is v at the identity grid point)
    float dx = vol[vo + 0] * scale;
    float dy = vol[vo + 1] * scale;
    float dz = vol[vo + 2] * scale;

    // Sample location = identity + disp, clamped (matches reference clip)
    float lx = fminf(fmaxf((float)x + dx, 0.0f), (float)(VD - 1));
    float ly = fminf(fmaxf((float)y + dy, 0.0f), (float)(VH - 1));
    float lz = fminf(fmaxf((float)z + dz, 0.0f), (float)(VW - 1));

    float fx = floorf(lx), fy = floorf(ly), fz = floorf(lz);
    float wx = lx - fx,  wy = ly - fy,  wz = lz - fz;

    int x0 = (int)fx, y0 = (int)fy, z0 = (int)fz;
    int x1 = min(x0 + 1, VD - 1);
    int y1 = min(y0 + 1, VH - 1);
    int z1 = min(z0 + 1, VW - 1);

    // Row bases for the 4 (x,y) corner rows
    unsigned rb00 = ((unsigned)x0 * VH + (unsigned)y0) * VW;
    unsigned rb01 = ((unsigned)x0 * VH + (unsigned)y1) * VW;
    unsigned rb10 = ((unsigned)x1 * VH + (unsigned)y0) * VW;
    unsigned rb11 = ((unsigned)x1 * VH + (unsigned)y1) * VW;

    unsigned o000 = (rb00 + (unsigned)z0) * 3, o001 = (rb00 + (unsigned)z1) * 3;
    unsigned o010 = (rb01 + (unsigned)z0) * 3, o011 = (rb01 + (unsigned)z1) * 3;
    unsigned o100 = (rb10 + (unsigned)z0) * 3, o101 = (rb10 + (unsigned)z1) * 3;
    unsigned o110 = (rb11 + (unsigned)z0) * 3, o111 = (rb11 + (unsigned)z1) * 3;

    float owz = 1.0f - wz, owy = 1.0f - wy, owx = 1.0f - wx;

    float s[3];
#pragma unroll
    for (int c = 0; c < 3; c++) {
        float g000 = vol[o000 + c], g001 = vol[o001 + c];
        float g010 = vol[o010 + c], g011 = vol[o011 + c];
        float g100 = vol[o100 + c], g101 = vol[o101 + c];
        float g110 = vol[o110 + c], g111 = vol[o111 + c];

        float c00 = g000 * owz + g001 * wz;
        float c01 = g010 * owz + g011 * wz;
        float c10 = g100 * owz + g101 * wz;
        float c11 = g110 * owz + g111 * wz;

        float c0 = c00 * owy + c01 * wy;
        float c1 = c10 * owy + c11 * wy;
        s[c] = (c0 * owx + c1 * wx) * scale;
    }

    float* __restrict__ out = dst + (size_t)b * NVOX * 3 + vo;
    out[0] = dx + s[0];
    out[1] = dy + s[1];
    out[2] = dz + s[2];
}

extern "C" void kernel_launch(void* const* d_in, const int* in_sizes, int n_in,
                              void* d_out, int out_size)
{
    const float* vel = (const float*)d_in[0];
    float* out = (float*)d_out;
    float* scr = nullptr;
    cudaGetSymbolAddress((void**)&scr, g_scratch);

    const int threads = 256;
    const int blocks = (NTOT + threads - 1) / threads;
    const float s0 = 1.0f / 128.0f;   // OUT_TIME_PT / 2^INT_STEPS

    // 7 scaling-and-squaring steps; scale fused into step 1.
    vint_step<<<blocks, threads>>>(vel, out, s0);
    vint_step<<<blocks, threads>>>(out, scr, 1.0f);
    vint_step<<<blocks, threads>>>(scr, out, 1.0f);
    vint_step<<<blocks, threads>>>(out, scr, 1.0f);
    vint_step<<<blocks, threads>>>(scr, out, 1.0f);
    vint_step<<<blocks, threads>>>(out, scr, 1.0f);
    vint_step<<<blocks, threads>>>(scr, out, 1.0f);
}

// round 5
// speedup vs baseline: 1.1114x; 1.1114x over previous
#include <cuda_runtime.h>

#define VD 160
#define VH 192
#define VW 160
#define NB 2
#define NVOX (VD * VH * VW)          // 4,915,200 voxels per batch
#define NTOT (NB * NVOX)             // 9,830,400

// Two SoA ping-pong scratch buffers, each [NB][3][NVOX] floats (118 MB).
__device__ float g_a[(size_t)NTOT * 3];
__device__ float g_b[(size_t)NTOT * 3];

// AoS -> SoA transpose with fused initial scale (vel / 2^7).
// One thread per scalar element: read fully coalesced, write near-coalesced.
__global__ void __launch_bounds__(256)
transpose_scale(const float* __restrict__ in, float* __restrict__ out, float scale)
{
    unsigned i = blockIdx.x * 256u + threadIdx.x;
    if (i >= (unsigned)(NTOT * 3)) return;
    unsigned b = i / (unsigned)(NVOX * 3);
    unsigned e = i - b * (unsigned)(NVOX * 3);
    unsigned v = e / 3u;
    unsigned c = e - v * 3u;
    out[(size_t)b * NVOX * 3 + (size_t)c * NVOX + v] = in[i] * scale;
}

// One scaling-and-squaring step on SoA data.
// AOS_OUT=1: write AoS (final step into d_out). AOS_OUT=0: write SoA.
template <int AOS_OUT>
__global__ void __launch_bounds__(256)
vint_step_soa(const float* __restrict__ src, float* __restrict__ dst)
{
    unsigned idx = blockIdx.x * 256u + threadIdx.x;
    if (idx >= (unsigned)NTOT) return;

    unsigned b = idx / (unsigned)NVOX;
    unsigned v = idx - b * (unsigned)NVOX;

    unsigned z = v % VW;
    unsigned t = v / VW;
    unsigned y = t % VH;
    unsigned x = t / VH;

    const float* __restrict__ p0 = src + (size_t)b * NVOX * 3;       // x-channel plane
    const float* __restrict__ p1 = p0 + NVOX;                         // y-channel plane
    const float* __restrict__ p2 = p0 + 2 * NVOX;                     // z-channel plane

    // Center displacement
    float dx = p0[v];
    float dy = p1[v];
    float dz = p2[v];

    // Sample location = identity + disp, clamped
    float lx = fminf(fmaxf((float)x + dx, 0.0f), (float)(VD - 1));
    float ly = fminf(fmaxf((float)y + dy, 0.0f), (float)(VH - 1));
    float lz = fminf(fmaxf((float)z + dz, 0.0f), (float)(VW - 1));

    float fx = floorf(lx), fy = floorf(ly), fz = floorf(lz);
    float wx = lx - fx,  wy = ly - fy,  wz = lz - fz;

    int x0 = (int)fx, y0 = (int)fy, z0 = (int)fz;
    int x1 = min(x0 + 1, VD - 1);
    int y1 = min(y0 + 1, VH - 1);
    int z1 = min(z0 + 1, VW - 1);

    unsigned rb00 = ((unsigned)x0 * VH + (unsigned)y0) * VW;
    unsigned rb01 = ((unsigned)x0 * VH + (unsigned)y1) * VW;
    unsigned rb10 = ((unsigned)x1 * VH + (unsigned)y0) * VW;
    unsigned rb11 = ((unsigned)x1 * VH + (unsigned)y1) * VW;

    unsigned o000 = rb00 + (unsigned)z0, o001 = rb00 + (unsigned)z1;
    unsigned o010 = rb01 + (unsigned)z0, o011 = rb01 + (unsigned)z1;
    unsigned o100 = rb10 + (unsigned)z0, o101 = rb10 + (unsigned)z1;
    unsigned o110 = rb11 + (unsigned)z0, o111 = rb11 + (unsigned)z1;

    float owz = 1.0f - wz, owy = 1.0f - wy, owx = 1.0f - wx;

    float s[3];
    const float* planes[3] = {p0, p1, p2};
#pragma unroll
    for (int c = 0; c < 3; c++) {
        const float* __restrict__ pl = planes[c];
        float g000 = pl[o000], g001 = pl[o001];
        float g010 = pl[o010], g011 = pl[o011];
        float g100 = pl[o100], g101 = pl[o101];
        float g110 = pl[o110], g111 = pl[o111];

        float c00 = g000 * owz + g001 * wz;
        float c01 = g010 * owz + g011 * wz;
        float c10 = g100 * owz + g101 * wz;
        float c11 = g110 * owz + g111 * wz;

        float c0 = c00 * owy + c01 * wy;
        float c1 = c10 * owy + c11 * wy;
        s[c] = c0 * owx + c1 * wx;
    }

    if (AOS_OUT) {
        float* __restrict__ out = dst + ((size_t)b * NVOX + v) * 3;
        out[0] = dx + s[0];
        out[1] = dy + s[1];
        out[2] = dz + s[2];
    } else {
        float* __restrict__ out = dst + (size_t)b * NVOX * 3;
        out[v]            = dx + s[0];
        out[v + NVOX]     = dy + s[1];
        out[v + 2 * NVOX] = dz + s[2];
    }
}

extern "C" void kernel_launch(void* const* d_in, const int* in_sizes, int n_in,
                              void* d_out, int out_size)
{
    const float* vel = (const float*)d_in[0];
    float* out = (float*)d_out;
    float *a = nullptr, *bb = nullptr;
    cudaGetSymbolAddress((void**)&a, g_a);
    cudaGetSymbolAddress((void**)&bb, g_b);

    const int threads = 256;
    const int blocksV = (NTOT + threads - 1) / threads;
    const int blocksE = (NTOT * 3 + threads - 1) / threads;
    const float s0 = 1.0f / 128.0f;   // OUT_TIME_PT / 2^INT_STEPS

    // v0 = vel / 128, transposed to SoA
    transpose_scale<<<blocksE, threads>>>(vel, a, s0);
    // 7 squaring steps; last one writes AoS directly into d_out
    vint_step_soa<0><<<blocksV, threads>>>(a, bb);
    vint_step_soa<0><<<blocksV, threads>>>(bb, a);
    vint_step_soa<0><<<blocksV, threads>>>(a, bb);
    vint_step_soa<0><<<blocksV, threads>>>(bb, a);
    vint_step_soa<0><<<blocksV, threads>>>(a, bb);
    vint_step_soa<0><<<blocksV, threads>>>(bb, a);
    vint_step_soa<1><<<blocksV, threads>>>(a, out);
}